// round 16
// baseline (speedup 1.0000x reference)
#include <cuda_runtime.h>
#include <cuda.h>
#include <cuda_fp16.h>
#include <stdint.h>
#include <math.h>

// ---------------------------------------------------------------------------
// Shapes (fixed)
#define TOK   4096
#define DIN   4096
#define DOUT  4096
#define ELEMS ((size_t)DOUT * (size_t)DIN)

#define FAST_DECAY 0.95f
#define FAST_LR    0.05f
#define SLOW_DECAY 0.99f
#define SLOW_LR    0.01f
#define HOMEO_TARGET 5.0

// fp16 GEMM. CTA tile 64x128x64, 8 warps (2m x 4n), warp tile 32x32,
// TMA + 3-stage full/empty mbarrier pipeline, 3 CTAs/SM (regs<=85).
#define BK       64
#define NCHUNK   (4096 / BK)         // 64
#define NTILES   2048                // 64 m-tiles x 32 n-tiles
#define TILE_A   8192                // 64 rows x 128B
#define TILE_BB  16384               // 128 rows x 128B
#define STAGE_B  (TILE_A + TILE_BB)  // 24576
#define NSTAGE   3
#define DYN_SMEM (1024 + NSTAGE * STAGE_B + 2048)  // bars/align + stages + dred reuse pad

// ---------------------------------------------------------------------------
// Scratch
__device__ __half g_wh[ELEMS];       // w_eff fp16, K-major
__device__ __half g_xh[ELEMS];       // X fp16 [TOK, DIN]
__device__ __half g_yrh[ELEMS];      // relu(Y) fp16 [TOK, DOUT]
__device__ double g_partials[NTILES];
__device__ float  g_factor;

// ---------------------------------------------------------------------------
__device__ __forceinline__ uint32_t smem_u32(const void* p) {
    uint32_t a;
    asm("{ .reg .u64 t; cvta.to.shared.u64 t, %1; cvt.u32.u64 %0, t; }" : "=r"(a) : "l"(p));
    return a;
}
__device__ __forceinline__ void mma_f16(float* c, const uint32_t* a, const uint32_t* b) {
    asm volatile(
        "mma.sync.aligned.m16n8k16.row.col.f32.f16.f16.f32 "
        "{%0,%1,%2,%3}, {%4,%5,%6,%7}, {%8,%9}, {%0,%1,%2,%3};"
        : "+f"(c[0]), "+f"(c[1]), "+f"(c[2]), "+f"(c[3])
        : "r"(a[0]), "r"(a[1]), "r"(a[2]), "r"(a[3]), "r"(b[0]), "r"(b[1]));
}
#define LDSM4(R, A) \
    asm volatile("ldmatrix.sync.aligned.m8n8.x4.shared.b16 {%0,%1,%2,%3}, [%4];" \
        : "=r"((R)[0]), "=r"((R)[1]), "=r"((R)[2]), "=r"((R)[3]) : "r"(A))
#define LDSM4T(R, A) \
    asm volatile("ldmatrix.sync.aligned.m8n8.x4.trans.shared.b16 {%0,%1,%2,%3}, [%4];" \
        : "=r"((R)[0]), "=r"((R)[1]), "=r"((R)[2]), "=r"((R)[3]) : "r"(A))

#define MBARRIER_INIT(addr, cnt) \
    asm volatile("mbarrier.init.shared.b64 [%0], %1;" :: "r"(addr), "r"((uint32_t)(cnt)) : "memory")
#define MBARRIER_ARRIVE(addr) \
    asm volatile("mbarrier.arrive.shared.b64 _, [%0];" :: "r"(addr) : "memory")
#define MBARRIER_EXPECT_TX(addr, bytes) \
    asm volatile("mbarrier.arrive.expect_tx.shared.b64 _, [%0], %1;" \
                 :: "r"(addr), "r"((uint32_t)(bytes)) : "memory")
#define MBARRIER_WAIT_PARITY(addr, par) do {                                          \
    uint32_t _m = (addr); uint32_t _p = (uint32_t)(par); uint32_t _d;                 \
    asm volatile("{\n\t.reg .pred p;\n\t"                                             \
        "mbarrier.try_wait.parity.acquire.cta.shared::cta.b64 p, [%1], %2;\n\t"       \
        "selp.b32 %0, 1, 0, p;\n\t}" : "=r"(_d) : "r"(_m), "r"(_p) : "memory");       \
    if (!_d) {                                                                        \
        asm volatile("{\n\t.reg .pred P1;\n\t"                                        \
            "W_%=:\n\t"                                                               \
            "mbarrier.try_wait.parity.acquire.cta.shared::cta.b64 P1, [%0], %1, 0x989680;\n\t" \
            "@P1 bra.uni D_%=;\n\t"                                                   \
            "bra.uni W_%=;\n\t"                                                       \
            "D_%=:\n\t}" :: "r"(_m), "r"(_p) : "memory");                             \
    }                                                                                 \
} while (0)

__device__ __forceinline__ void tma2d(uint32_t dst, const CUtensorMap* m,
                                      int cx, int cy, uint32_t mbar) {
    asm volatile(
        "cp.async.bulk.tensor.2d.shared::cta.global.tile.mbarrier::complete_tx::bytes "
        "[%0], [%1, {%2, %3}], [%4];"
        :: "r"(dst), "l"(m), "r"(cx), "r"(cy), "r"(mbar) : "memory");
}

// ---------------------------------------------------------------------------
// Fused prep: blocks [0,4096): per-row quantize+combine w_eff -> wh (fp16)
//             blocks [4096,20480): X -> xh (fp16)
__global__ __launch_bounds__(256) void k_prep(
    const float* __restrict__ w, const float* __restrict__ fast, const float* __restrict__ slow,
    const float* __restrict__ x,
    __half* __restrict__ wh, __half* __restrict__ xh)
{
    const int tid = threadIdx.x;
    if (blockIdx.x >= 4096) {
        const size_t i = ((size_t)(blockIdx.x - 4096) * 256 + tid) * 4;
        float4 v = *(const float4*)(x + i);
        union { __half h[4]; uint64_t u; } H;
        H.h[0] = __float2half_rn(v.x);
        H.h[1] = __float2half_rn(v.y);
        H.h[2] = __float2half_rn(v.z);
        H.h[3] = __float2half_rn(v.w);
        *(uint64_t*)(xh + i) = H.u;
        return;
    }
    const int row = blockIdx.x;
    const size_t base = (size_t)row * DIN;

    float s = 0.f;
    for (int i = tid; i < DIN; i += 256) s += fabsf(w[base + i]);
    __shared__ float red[256];
    red[tid] = s;
    __syncthreads();
    #pragma unroll
    for (int off = 128; off > 0; off >>= 1) {
        if (tid < off) red[tid] += red[tid + off];
        __syncthreads();
    }
    float scale = fmaxf(red[0] * (1.0f / (float)DIN), 1e-5f);
    const float inv_scale = 1.0f / scale;

    for (int i = tid; i < DIN; i += 256) {
        const size_t idx = base + i;
        float q = rintf(w[idx] * inv_scale);
        q = fminf(fmaxf(q, -1.0f), 1.0f);
        float v = q * scale + 0.1f * fast[idx] + 0.05f * slow[idx];
        wh[idx] = __float2half_rn(v);
    }
}

// ---------------------------------------------------------------------------
// fp16 GEMM, TMA + 3-stage full/empty mbarrier pipeline, fp32 accumulators.
// CTA 64x128, 8 warps (2m x 4n), warp tile 32x32, 3 CTAs/SM.
// MODE 0 (NT): A tile 64x128B, B tile 128x128B, SW128.
// MODE 1 (TT): A tile 64k x 64col, B 2 subtiles 64k x 64col, SW128, ldmatrix.trans.
// ---------------------------------------------------------------------------
template<int MODE>
__global__ __launch_bounds__(256, 3) void k_gemm_tma(
    const __grid_constant__ CUtensorMap mA, const __grid_constant__ CUtensorMap mB,
    const float* __restrict__ fast, float* __restrict__ out,
    __half* __restrict__ orelu)
{
    constexpr bool TRANS = (MODE == 1);

    extern __shared__ uint32_t dsm[];

    const int tid  = threadIdx.x;
    const int lane = tid & 31;
    const int wid  = tid >> 5;
    const int g    = lane >> 2;
    const int tig  = lane & 3;

    // supertile swizzle: 4 groups x (64 m-tiles x 8 n-tiles)
    const int bid   = blockIdx.x;
    const int group = bid >> 9;
    const int rem   = bid & 511;
    const int am  = (rem >> 3) * 64;
    const int bn  = (group * 8 + (rem & 7)) * 128;

    const int wm = (wid & 1) * 32;        // warp m offset
    const int wn = (wid >> 1) * 32;       // warp n offset

    const uint32_t sraw = smem_u32(dsm);
    const uint32_t sbase0 = (sraw + 1023u) & ~1023u;   // barrier block
    const uint32_t sbase  = sbase0 + 1024u;            // tile stages

    uint32_t mbf[NSTAGE], mbe[NSTAGE];
    #pragma unroll
    for (int s = 0; s < NSTAGE; s++) {
        mbf[s] = sbase0 + s * 8;
        mbe[s] = sbase0 + 64 + s * 8;
    }
    if (tid == 0) {
        #pragma unroll
        for (int s = 0; s < NSTAGE; s++) {
            MBARRIER_INIT(mbf[s], 1);
            MBARRIER_INIT(mbe[s], 8);
        }
    }
    __syncthreads();

    // ---- per-lane ldmatrix offsets ----
    uint32_t aoff[2], boff[2];
    uint32_t asw[2], bsw[2];                 // NT swizzle selectors (r & 7)
    const int ld_row = ((lane >> 3) & 1) * 8 + (lane & 7);
    const int lh = lane >> 4;                // 16B-unit select (NT)
    if (!TRANS) {
        #pragma unroll
        for (int mt = 0; mt < 2; mt++) {
            const int r = wm + mt * 16 + ld_row;     // < 64
            aoff[mt] = (uint32_t)(r * 128);
            asw[mt]  = (uint32_t)(r & 7);
        }
        #pragma unroll
        for (int p = 0; p < 2; p++) {
            const int r = wn + p * 16 + ld_row;      // < 128
            boff[p] = (uint32_t)(r * 128);
            bsw[p]  = (uint32_t)(r & 7);
        }
    } else {
        const int kr = (lane >> 4) * 8 + (lane & 7);   // k row 0..15
        const int cb16 = ((lane >> 3) & 1) * 16;       // 16B col half
        #pragma unroll
        for (int mt = 0; mt < 2; mt++) {
            const int colb = wm * 2 + mt * 32 + cb16;  // < 128 (single subtile)
            aoff[mt] = (uint32_t)(kr * 128 +
                                  (((colb >> 4) ^ (kr & 7)) << 4));
        }
        #pragma unroll
        for (int p = 0; p < 2; p++) {
            const int colb = wn * 2 + p * 32 + cb16;   // < 256 -> 2 subtiles
            boff[p] = (uint32_t)((colb >> 7) * 8192 + kr * 128 +
                                 ((((colb & 127) >> 4) ^ (kr & 7)) << 4));
        }
    }

    float acc[2][4][4];
    #pragma unroll
    for (int mt = 0; mt < 2; mt++)
        #pragma unroll
        for (int nt = 0; nt < 4; nt++)
            #pragma unroll
            for (int r = 0; r < 4; r++) acc[mt][nt][r] = 0.f;

    // ---- TMA issue helper (thread 0 only) ----
    auto issue = [&](int stage, int chunk) {
        const uint32_t sdst = sbase + (uint32_t)stage * STAGE_B;
        MBARRIER_EXPECT_TX(mbf[stage], STAGE_B);
        const int k0 = chunk * BK;
        if (!TRANS) {
            tma2d(sdst,          &mA, k0, am, mbf[stage]);
            tma2d(sdst + TILE_A, &mB, k0, bn, mbf[stage]);
        } else {
            tma2d(sdst,                 &mA, am,      k0, mbf[stage]);
            tma2d(sdst + TILE_A,        &mB, bn,      k0, mbf[stage]);
            tma2d(sdst + TILE_A + 8192, &mB, bn + 64, k0, mbf[stage]);
        }
    };

    if (tid == 0) { issue(0, 0); issue(1, 1); }

    int sc = 0;
    uint32_t phb = 0;        // per-warp full-barrier phase bits
    for (int c = 0; c < NCHUNK; c++) {
        if (tid == 0 && c + 2 < NCHUNK) {
            const int cc = c + 2;
            int sn = sc + 2; if (sn >= NSTAGE) sn -= NSTAGE;
            const int u = cc / NSTAGE;
            if (u >= 1) MBARRIER_WAIT_PARITY(mbe[sn], (uint32_t)((u - 1) & 1));
            issue(sn, cc);
        }

        MBARRIER_WAIT_PARITY(mbf[sc], (phb >> sc) & 1u);
        phb ^= (1u << sc);

        const uint32_t stg = sbase + (uint32_t)sc * STAGE_B;
        #pragma unroll
        for (int ks = 0; ks < 4; ks++) {
            uint32_t a[2][4];
            #pragma unroll
            for (int mt = 0; mt < 2; mt++) {
                uint32_t addr;
                if (!TRANS)
                    addr = stg + aoff[mt] +
                           ((((uint32_t)(ks * 2 + lh)) ^ asw[mt]) << 4);
                else
                    addr = stg + aoff[mt] + ks * 2048;
                if (!TRANS) { LDSM4(a[mt], addr); } else { LDSM4T(a[mt], addr); }
            }
            uint32_t b[2][4];
            #pragma unroll
            for (int p = 0; p < 2; p++) {
                uint32_t addr;
                if (!TRANS)
                    addr = stg + TILE_A + boff[p] +
                           ((((uint32_t)(ks * 2 + lh)) ^ bsw[p]) << 4);
                else
                    addr = stg + TILE_A + boff[p] + ks * 2048;
                if (!TRANS) { LDSM4(b[p], addr); } else { LDSM4T(b[p], addr); }
            }
            #pragma unroll
            for (int p = 0; p < 2; p++) {
                uint32_t b0[2] = {b[p][0], b[p][2]}, b1[2] = {b[p][1], b[p][3]};
                mma_f16(acc[0][2*p],   a[0], b0);
                mma_f16(acc[0][2*p+1], a[0], b1);
                mma_f16(acc[1][2*p],   a[1], b0);
                mma_f16(acc[1][2*p+1], a[1], b1);
            }
        }
        if (lane == 0) MBARRIER_ARRIVE(mbe[sc]);
        sc = (sc == NSTAGE - 1) ? 0 : sc + 1;
    }

    // ---- epilogue ----
    double ss = 0.0;
    const float inv_tok = 1.0f / (float)TOK;
    #pragma unroll
    for (int mt = 0; mt < 2; mt++) {
        const int r0 = am + wm + mt * 16 + g;
        #pragma unroll
        for (int nt = 0; nt < 4; nt++) {
            const int col = bn + wn + nt * 8 + tig * 2;
            #pragma unroll
            for (int half = 0; half < 2; half++) {
                const int r = r0 + half * 8;
                const float d0 = acc[mt][nt][half * 2 + 0];
                const float d1 = acc[mt][nt][half * 2 + 1];
                const size_t o = (size_t)r * 4096 + col;
                if (MODE == 0) {
                    *(float2*)(out + o) = make_float2(d0, d1);
                    union { __half h[2]; uint32_t u; } R;
                    R.h[0] = __float2half_rn(fmaxf(d0, 0.f));
                    R.h[1] = __float2half_rn(fmaxf(d1, 0.f));
                    *(uint32_t*)(orelu + o) = R.u;
                } else {
                    const float2 fa = *(const float2*)(fast + o);
                    float2 v;
                    v.x = FAST_DECAY * fa.x + FAST_LR * (d0 * inv_tok);
                    v.y = FAST_DECAY * fa.y + FAST_LR * (d1 * inv_tok);
                    *(float2*)(out + o) = v;
                    ss += (double)v.x * v.x + (double)v.y * v.y;
                }
            }
        }
    }
    if (MODE == 1) {
        // reuse tile smem for the reduction; guard against lagging warps
        __syncthreads();
        double* dred = (double*)(dsm + ((sbase - sraw) >> 2) + 256);  // within stage area
        dred[tid] = ss;
        __syncthreads();
        #pragma unroll
        for (int off = 128; off > 0; off >>= 1) {
            if (tid < off) dred[tid] += dred[tid + off];
            __syncthreads();
        }
        if (tid == 0) g_partials[blockIdx.x] = dred[0];
    }
}

// ---------------------------------------------------------------------------
__global__ void k_norm_factor()
{
    __shared__ double red[256];
    const int tid = threadIdx.x;
    double s = 0.0;
    for (int i = tid; i < NTILES; i += 256) s += g_partials[i];
    red[tid] = s;
    __syncthreads();
    #pragma unroll
    for (int off = 128; off > 0; off >>= 1) {
        if (tid < off) red[tid] += red[tid + off];
        __syncthreads();
    }
    if (tid == 0) {
        const double norm = sqrt(red[0]);
        g_factor = (norm > HOMEO_TARGET) ? (float)(HOMEO_TARGET / (norm + 1e-6)) : 1.0f;
    }
}

__global__ __launch_bounds__(256) void k_finalize(
    const float* __restrict__ slow, float* __restrict__ fout, float* __restrict__ sout)
{
    const float fac = g_factor;
    const size_t i = (size_t)blockIdx.x * blockDim.x + threadIdx.x;
    float4 f = ((const float4*)fout)[i];
    f.x *= fac; f.y *= fac; f.z *= fac; f.w *= fac;
    ((float4*)fout)[i] = f;
    const float4 sl = ((const float4*)slow)[i];
    float4 so;
    so.x = SLOW_DECAY * sl.x + SLOW_LR * f.x;
    so.y = SLOW_DECAY * sl.y + SLOW_LR * f.y;
    so.z = SLOW_DECAY * sl.z + SLOW_LR * f.z;
    so.w = SLOW_DECAY * sl.w + SLOW_LR * f.w;
    ((float4*)sout)[i] = so;
}

// ---------------------------------------------------------------------------
typedef CUresult (*PFN_tmEncode)(
    CUtensorMap*, CUtensorMapDataType, cuuint32_t, void*,
    const cuuint64_t*, const cuuint64_t*, const cuuint32_t*, const cuuint32_t*,
    CUtensorMapInterleave, CUtensorMapSwizzle, CUtensorMapL2promotion,
    CUtensorMapFloatOOBfill);

static void make_map(PFN_tmEncode enc, CUtensorMap* m, void* ptr,
                     int box_inner, int box_outer)
{
    cuuint64_t dims[2]    = {4096, 4096};
    cuuint64_t strides[1] = {4096 * 2};
    cuuint32_t box[2]     = {(cuuint32_t)box_inner, (cuuint32_t)box_outer};
    cuuint32_t est[2]     = {1, 1};
    enc(m, CU_TENSOR_MAP_DATA_TYPE_FLOAT16, 2, ptr, dims, strides, box, est,
        CU_TENSOR_MAP_INTERLEAVE_NONE, CU_TENSOR_MAP_SWIZZLE_128B,
        CU_TENSOR_MAP_L2_PROMOTION_L2_128B, CU_TENSOR_MAP_FLOAT_OOB_FILL_NONE);
}

extern "C" void kernel_launch(void* const* d_in, const int* in_sizes, int n_in,
                              void* d_out, int out_size)
{
    const float* x    = (const float*)d_in[0];
    const float* w    = (const float*)d_in[1];
    const float* fast = (const float*)d_in[2];
    const float* slow = (const float*)d_in[3];

    float* out   = (float*)d_out;
    float* y_out = out;
    float* f_out = out + (size_t)TOK * DOUT;
    float* s_out = f_out + ELEMS;

    __half *wh, *xh, *yrh;
    cudaGetSymbolAddress((void**)&wh,  g_wh);
    cudaGetSymbolAddress((void**)&xh,  g_xh);
    cudaGetSymbolAddress((void**)&yrh, g_yrh);

    void* sym = nullptr;
    cudaDriverEntryPointQueryResult qr;
    cudaGetDriverEntryPoint("cuTensorMapEncodeTiled", &sym, cudaEnableDefault, &qr);
    PFN_tmEncode enc = (PFN_tmEncode)sym;

    // NT maps (GEMM1): A box {64 k, 64 rows}; B box {64 k, 128 rows}
    CUtensorMap mX, mW;
    make_map(enc, &mX, xh, 64, 64);
    make_map(enc, &mW, wh, 64, 128);
    // TT maps (GEMM2): box {64 cols, 64 k-rows} for both operands
    CUtensorMap mY, mXT;
    make_map(enc, &mY,  yrh, 64, 64);
    make_map(enc, &mXT, xh,  64, 64);

    cudaFuncSetAttribute(k_gemm_tma<0>, cudaFuncAttributeMaxDynamicSharedMemorySize, DYN_SMEM);
    cudaFuncSetAttribute(k_gemm_tma<1>, cudaFuncAttributeMaxDynamicSharedMemorySize, DYN_SMEM);

    // 1) fused prep: w_eff quantize->fp16 AND X->fp16
    k_prep<<<4096 + 16384, 256>>>(w, fast, slow, x, wh, xh);
    // 2) Y = X @ w_eff^T; epilogue emits y fp32 + relu(Y) fp16
    k_gemm_tma<0><<<NTILES, 256, DYN_SMEM>>>(mX, mW, nullptr, y_out, yrh);
    // 3) new_fast (unscaled) = 0.95*fast + 0.05*(reluY^T @ X)/TOK, + partials
    k_gemm_tma<1><<<NTILES, 256, DYN_SMEM>>>(mY, mXT, fast, f_out, nullptr);
    // 4) norm -> factor
    k_norm_factor<<<1, 256>>>();
    // 5) scale fast, compute slow
    k_finalize<<<(unsigned)(ELEMS / 4 / 256), 256>>>(slow, f_out, s_out);
}

// round 17
// speedup vs baseline: 1.0553x; 1.0553x over previous
#include <cuda_runtime.h>
#include <cuda.h>
#include <cuda_fp16.h>
#include <stdint.h>
#include <math.h>

// ---------------------------------------------------------------------------
// Shapes (fixed)
#define TOK   4096
#define DIN   4096
#define DOUT  4096
#define ELEMS ((size_t)DOUT * (size_t)DIN)

#define FAST_DECAY 0.95f
#define FAST_LR    0.05f
#define SLOW_DECAY 0.99f
#define SLOW_LR    0.01f
#define HOMEO_TARGET 5.0

// fp16 single-term GEMM. CTA tile 128x128x64, 8 warps (4m x 2n), warp 32x64,
// TMA + 3-stage full/empty mbarrier pipeline, 2 CTAs/SM.  (round-15 champion)
#define BK       64
#define NCHUNK   (4096 / BK)         // 64
#define NTILES   1024
#define TILE_B   16384               // one operand tile: 128 rows x 128B (SW128)
#define STAGE_B  (2 * TILE_B)        // A + B = 32KB
#define NSTAGE   3
#define DYN_SMEM (NSTAGE * STAGE_B + 1024)   // 99328; x2 CTAs = 198656 < 228KB

// ---------------------------------------------------------------------------
// Scratch
__device__ __half g_wh[ELEMS];       // w_eff fp16, K-major
__device__ __half g_xh[ELEMS];       // X fp16 [TOK, DIN]
__device__ __half g_yrh[ELEMS];      // relu(Y) fp16 [TOK, DOUT]
__device__ double g_partials[NTILES];
__device__ float  g_factor;

// ---------------------------------------------------------------------------
__device__ __forceinline__ uint32_t smem_u32(const void* p) {
    uint32_t a;
    asm("{ .reg .u64 t; cvta.to.shared.u64 t, %1; cvt.u32.u64 %0, t; }" : "=r"(a) : "l"(p));
    return a;
}
__device__ __forceinline__ void mma_f16(float* c, const uint32_t* a, const uint32_t* b) {
    asm volatile(
        "mma.sync.aligned.m16n8k16.row.col.f32.f16.f16.f32 "
        "{%0,%1,%2,%3}, {%4,%5,%6,%7}, {%8,%9}, {%0,%1,%2,%3};"
        : "+f"(c[0]), "+f"(c[1]), "+f"(c[2]), "+f"(c[3])
        : "r"(a[0]), "r"(a[1]), "r"(a[2]), "r"(a[3]), "r"(b[0]), "r"(b[1]));
}
#define LDSM4(R, A) \
    asm volatile("ldmatrix.sync.aligned.m8n8.x4.shared.b16 {%0,%1,%2,%3}, [%4];" \
        : "=r"((R)[0]), "=r"((R)[1]), "=r"((R)[2]), "=r"((R)[3]) : "r"(A))
#define LDSM4T(R, A) \
    asm volatile("ldmatrix.sync.aligned.m8n8.x4.trans.shared.b16 {%0,%1,%2,%3}, [%4];" \
        : "=r"((R)[0]), "=r"((R)[1]), "=r"((R)[2]), "=r"((R)[3]) : "r"(A))

#define MBARRIER_INIT(addr, cnt) \
    asm volatile("mbarrier.init.shared.b64 [%0], %1;" :: "r"(addr), "r"((uint32_t)(cnt)) : "memory")
#define MBARRIER_ARRIVE(addr) \
    asm volatile("mbarrier.arrive.shared.b64 _, [%0];" :: "r"(addr) : "memory")
#define MBARRIER_EXPECT_TX(addr, bytes) \
    asm volatile("mbarrier.arrive.expect_tx.shared.b64 _, [%0], %1;" \
                 :: "r"(addr), "r"((uint32_t)(bytes)) : "memory")
#define MBARRIER_WAIT_PARITY(addr, par) do {                                          \
    uint32_t _m = (addr); uint32_t _p = (uint32_t)(par); uint32_t _d;                 \
    asm volatile("{\n\t.reg .pred p;\n\t"                                             \
        "mbarrier.try_wait.parity.acquire.cta.shared::cta.b64 p, [%1], %2;\n\t"       \
        "selp.b32 %0, 1, 0, p;\n\t}" : "=r"(_d) : "r"(_m), "r"(_p) : "memory");       \
    if (!_d) {                                                                        \
        asm volatile("{\n\t.reg .pred P1;\n\t"                                        \
            "W_%=:\n\t"                                                               \
            "mbarrier.try_wait.parity.acquire.cta.shared::cta.b64 P1, [%0], %1, 0x989680;\n\t" \
            "@P1 bra.uni D_%=;\n\t"                                                   \
            "bra.uni W_%=;\n\t"                                                       \
            "D_%=:\n\t}" :: "r"(_m), "r"(_p) : "memory");                             \
    }                                                                                 \
} while (0)

__device__ __forceinline__ void tma2d(uint32_t dst, const CUtensorMap* m,
                                      int cx, int cy, uint32_t mbar) {
    asm volatile(
        "cp.async.bulk.tensor.2d.shared::cta.global.tile.mbarrier::complete_tx::bytes "
        "[%0], [%1, {%2, %3}], [%4];"
        :: "r"(dst), "l"(m), "r"(cx), "r"(cy), "r"(mbar) : "memory");
}

// ---------------------------------------------------------------------------
// Fused prep: blocks [0,4096): per-row quantize+combine w_eff -> wh (fp16)
//             (w row cached in smem: one gmem read instead of two)
//             blocks [4096,20480): X -> xh (fp16)
__global__ __launch_bounds__(256) void k_prep(
    const float* __restrict__ w, const float* __restrict__ fast, const float* __restrict__ slow,
    const float* __restrict__ x,
    __half* __restrict__ wh, __half* __restrict__ xh)
{
    const int tid = threadIdx.x;
    if (blockIdx.x >= 4096) {
        const size_t i = ((size_t)(blockIdx.x - 4096) * 256 + tid) * 4;
        float4 v = *(const float4*)(x + i);
        union { __half h[4]; uint64_t u; } H;
        H.h[0] = __float2half_rn(v.x);
        H.h[1] = __float2half_rn(v.y);
        H.h[2] = __float2half_rn(v.z);
        H.h[3] = __float2half_rn(v.w);
        *(uint64_t*)(xh + i) = H.u;
        return;
    }
    __shared__ float wrow[DIN];          // 16KB row cache
    __shared__ float red[256];

    const int row = blockIdx.x;
    const size_t base = (size_t)row * DIN;

    float s = 0.f;
    for (int i = tid * 4; i < DIN; i += 1024) {
        float4 v = *(const float4*)(w + base + i);
        *(float4*)(wrow + i) = v;
        s += fabsf(v.x) + fabsf(v.y) + fabsf(v.z) + fabsf(v.w);
    }
    red[tid] = s;
    __syncthreads();
    #pragma unroll
    for (int off = 128; off > 0; off >>= 1) {
        if (tid < off) red[tid] += red[tid + off];
        __syncthreads();
    }
    float scale = fmaxf(red[0] * (1.0f / (float)DIN), 1e-5f);
    const float inv_scale = 1.0f / scale;

    for (int i = tid; i < DIN; i += 256) {
        const size_t idx = base + i;
        float q = rintf(wrow[i] * inv_scale);
        q = fminf(fmaxf(q, -1.0f), 1.0f);
        float v = q * scale + 0.1f * fast[idx] + 0.05f * slow[idx];
        wh[idx] = __float2half_rn(v);
    }
}

// ---------------------------------------------------------------------------
// fp16 GEMM, TMA + 3-stage full/empty mbarrier pipeline, fp32 accumulators.
// TMA-issue duty rotates across warps (wid == c & 7) to spread producer stalls.
// MODE 0 (NT): tiles 128 rows x 128B (64 k-elems), SW128.
// MODE 1 (TT): 2 subtiles of 64 k-rows x 128B (64 cols), SW128, ldmatrix.trans.
// ---------------------------------------------------------------------------
template<int MODE>
__global__ __launch_bounds__(256, 2) void k_gemm_tma(
    const __grid_constant__ CUtensorMap mA, const __grid_constant__ CUtensorMap mB,
    const float* __restrict__ fast, float* __restrict__ out,
    __half* __restrict__ orelu)
{
    constexpr bool TRANS = (MODE == 1);

    extern __shared__ uint32_t dsm[];
    __shared__ double dred[256];
    __shared__ __align__(8) uint64_t mbars[2 * NSTAGE];   // [0..2]=full, [3..5]=empty

    const int tid  = threadIdx.x;
    const int lane = tid & 31;
    const int wid  = tid >> 5;
    const int g    = lane >> 2;
    const int tig  = lane & 3;

    // supertile swizzle: 4 groups x (32 m-tiles x 8 n-tiles)
    const int bid   = blockIdx.x;
    const int group = bid >> 8;
    const int rem   = bid & 255;
    const int am  = (rem >> 3) * 128;
    const int bn  = (group * 8 + (rem & 7)) * 128;

    const int wm = (wid & 3) * 32;
    const int wn = (wid >> 2) * 64;

    const uint32_t sraw = smem_u32(dsm);
    const uint32_t sbase = (sraw + 1023u) & ~1023u;

    uint32_t mbf[NSTAGE], mbe[NSTAGE];
    #pragma unroll
    for (int s = 0; s < NSTAGE; s++) {
        mbf[s] = smem_u32(&mbars[s]);
        mbe[s] = smem_u32(&mbars[NSTAGE + s]);
    }
    if (tid == 0) {
        #pragma unroll
        for (int s = 0; s < NSTAGE; s++) {
            MBARRIER_INIT(mbf[s], 1);
            MBARRIER_INIT(mbe[s], 8);    // one arrive per warp
        }
    }
    __syncthreads();

    // ---- per-lane ldmatrix offsets ----
    uint32_t aoff[2], boff[4];
    uint32_t asw[2], bsw[4];                 // NT swizzle selectors (r & 7)
    const int ld_row = ((lane >> 3) & 1) * 8 + (lane & 7);
    const int lh = lane >> 4;                // 16B-unit select (NT)
    if (!TRANS) {
        #pragma unroll
        for (int mt = 0; mt < 2; mt++) {
            const int r = wm + mt * 16 + ld_row;
            aoff[mt] = (uint32_t)(r * 128);
            asw[mt]  = (uint32_t)(r & 7);
        }
        #pragma unroll
        for (int p = 0; p < 4; p++) {
            const int r = wn + p * 16 + ld_row;
            boff[p] = (uint32_t)(r * 128);
            bsw[p]  = (uint32_t)(r & 7);
        }
    } else {
        const int kr = (lane >> 4) * 8 + (lane & 7);   // k row 0..15
        const int cb16 = ((lane >> 3) & 1) * 16;       // 16B col half
        #pragma unroll
        for (int mt = 0; mt < 2; mt++) {
            const int colb = wm * 2 + mt * 32 + cb16;  // byte col 0..255
            aoff[mt] = (uint32_t)((colb >> 7) * 8192 + kr * 128 +
                                  ((((colb & 127) >> 4) ^ (kr & 7)) << 4));
        }
        #pragma unroll
        for (int p = 0; p < 4; p++) {
            const int colb = wn * 2 + p * 32 + cb16;
            boff[p] = (uint32_t)((colb >> 7) * 8192 + kr * 128 +
                                 ((((colb & 127) >> 4) ^ (kr & 7)) << 4));
        }
    }

    float acc[2][8][4];
    #pragma unroll
    for (int mt = 0; mt < 2; mt++)
        #pragma unroll
        for (int nt = 0; nt < 8; nt++)
            #pragma unroll
            for (int r = 0; r < 4; r++) acc[mt][nt][r] = 0.f;

    // ---- TMA issue helper (one elected thread) ----
    auto issue = [&](int stage, int chunk) {
        const uint32_t sdst = sbase + (uint32_t)stage * STAGE_B;
        MBARRIER_EXPECT_TX(mbf[stage], STAGE_B);
        const int k0 = chunk * BK;
        if (!TRANS) {
            tma2d(sdst,          &mA, k0, am, mbf[stage]);
            tma2d(sdst + TILE_B, &mB, k0, bn, mbf[stage]);
        } else {
            tma2d(sdst,                 &mA, am,      k0, mbf[stage]);
            tma2d(sdst + 8192,          &mA, am + 64, k0, mbf[stage]);
            tma2d(sdst + TILE_B,        &mB, bn,      k0, mbf[stage]);
            tma2d(sdst + TILE_B + 8192, &mB, bn + 64, k0, mbf[stage]);
        }
    };

    if (tid == 0) { issue(0, 0); issue(1, 1); }

    int sc = 0;
    uint32_t phb = 0;        // per-warp full-barrier phase bits
    for (int c = 0; c < NCHUNK; c++) {
        // Rotating producer: warp (c & 7) lane 0 refills 2 chunks ahead.
        // Must wait until ALL warps released stage (c+2)%3 (parity is absolute,
        // derived from chunk index, so any warp may do the wait).
        if (wid == (c & 7) && lane == 0 && c + 2 < NCHUNK) {
            const int cc = c + 2;
            int sn = sc + 2; if (sn >= NSTAGE) sn -= NSTAGE;
            const int u = cc / NSTAGE;           // use index of this stage
            if (u >= 1) MBARRIER_WAIT_PARITY(mbe[sn], (uint32_t)((u - 1) & 1));
            issue(sn, cc);
        }

        // All warps: wait for chunk c's data (independent, no CTA barrier).
        MBARRIER_WAIT_PARITY(mbf[sc], (phb >> sc) & 1u);
        phb ^= (1u << sc);

        const uint32_t stg = sbase + (uint32_t)sc * STAGE_B;
        #pragma unroll
        for (int ks = 0; ks < 4; ks++) {
            uint32_t a[2][4];
            #pragma unroll
            for (int mt = 0; mt < 2; mt++) {
                uint32_t addr;
                if (!TRANS)
                    addr = stg + aoff[mt] +
                           ((((uint32_t)(ks * 2 + lh)) ^ asw[mt]) << 4);
                else
                    addr = stg + aoff[mt] + ks * 2048;
                if (!TRANS) { LDSM4(a[mt], addr); } else { LDSM4T(a[mt], addr); }
            }
            uint32_t b[4][4];
            #pragma unroll
            for (int p = 0; p < 4; p++) {
                uint32_t addr;
                if (!TRANS)
                    addr = stg + TILE_B + boff[p] +
                           ((((uint32_t)(ks * 2 + lh)) ^ bsw[p]) << 4);
                else
                    addr = stg + TILE_B + boff[p] + ks * 2048;
                if (!TRANS) { LDSM4(b[p], addr); } else { LDSM4T(b[p], addr); }
            }
            #pragma unroll
            for (int p = 0; p < 4; p++) {
                uint32_t b0[2] = {b[p][0], b[p][2]}, b1[2] = {b[p][1], b[p][3]};
                mma_f16(acc[0][2*p],   a[0], b0);
                mma_f16(acc[0][2*p+1], a[0], b1);
                mma_f16(acc[1][2*p],   a[1], b0);
                mma_f16(acc[1][2*p+1], a[1], b1);
            }
        }
        // this warp is done reading stage sc (LDSM results are in registers)
        if (lane == 0) MBARRIER_ARRIVE(mbe[sc]);
        sc = (sc == NSTAGE - 1) ? 0 : sc + 1;
    }

    // ---- epilogue ----
    double ss = 0.0;
    const float inv_tok = 1.0f / (float)TOK;
    #pragma unroll
    for (int mt = 0; mt < 2; mt++) {
        const int r0 = am + wm + mt * 16 + g;
        #pragma unroll
        for (int nt = 0; nt < 8; nt++) {
            const int col = bn + wn + nt * 8 + tig * 2;
            #pragma unroll
            for (int half = 0; half < 2; half++) {
                const int r = r0 + half * 8;
                const float d0 = acc[mt][nt][half * 2 + 0];
                const float d1 = acc[mt][nt][half * 2 + 1];
                const size_t o = (size_t)r * 4096 + col;
                if (MODE == 0) {
                    *(float2*)(out + o) = make_float2(d0, d1);
                    union { __half h[2]; uint32_t u; } R;
                    R.h[0] = __float2half_rn(fmaxf(d0, 0.f));
                    R.h[1] = __float2half_rn(fmaxf(d1, 0.f));
                    *(uint32_t*)(orelu + o) = R.u;
                } else {
                    const float2 fa = *(const float2*)(fast + o);
                    float2 v;
                    v.x = FAST_DECAY * fa.x + FAST_LR * (d0 * inv_tok);
                    v.y = FAST_DECAY * fa.y + FAST_LR * (d1 * inv_tok);
                    *(float2*)(out + o) = v;
                    ss += (double)v.x * v.x + (double)v.y * v.y;
                }
            }
        }
    }
    if (MODE == 1) {
        dred[tid] = ss;
        __syncthreads();
        #pragma unroll
        for (int off = 128; off > 0; off >>= 1) {
            if (tid < off) dred[tid] += dred[tid + off];
            __syncthreads();
        }
        if (tid == 0) g_partials[blockIdx.x] = dred[0];
    }
}

// ---------------------------------------------------------------------------
__global__ void k_norm_factor()
{
    __shared__ double red[256];
    const int tid = threadIdx.x;
    double s = 0.0;
    for (int i = tid; i < NTILES; i += 256) s += g_partials[i];
    red[tid] = s;
    __syncthreads();
    #pragma unroll
    for (int off = 128; off > 0; off >>= 1) {
        if (tid < off) red[tid] += red[tid + off];
        __syncthreads();
    }
    if (tid == 0) {
        const double norm = sqrt(red[0]);
        g_factor = (norm > HOMEO_TARGET) ? (float)(HOMEO_TARGET / (norm + 1e-6)) : 1.0f;
    }
}

__global__ __launch_bounds__(256) void k_finalize(
    const float* __restrict__ slow, float* __restrict__ fout, float* __restrict__ sout)
{
    const float fac = g_factor;
    const size_t i = (size_t)blockIdx.x * blockDim.x + threadIdx.x;
    float4 f = ((const float4*)fout)[i];
    f.x *= fac; f.y *= fac; f.z *= fac; f.w *= fac;
    ((float4*)fout)[i] = f;
    const float4 sl = ((const float4*)slow)[i];
    float4 so;
    so.x = SLOW_DECAY * sl.x + SLOW_LR * f.x;
    so.y = SLOW_DECAY * sl.y + SLOW_LR * f.y;
    so.z = SLOW_DECAY * sl.z + SLOW_LR * f.z;
    so.w = SLOW_DECAY * sl.w + SLOW_LR * f.w;
    ((float4*)sout)[i] = so;
}

// ---------------------------------------------------------------------------
typedef CUresult (*PFN_tmEncode)(
    CUtensorMap*, CUtensorMapDataType, cuuint32_t, void*,
    const cuuint64_t*, const cuuint64_t*, const cuuint32_t*, const cuuint32_t*,
    CUtensorMapInterleave, CUtensorMapSwizzle, CUtensorMapL2promotion,
    CUtensorMapFloatOOBfill);

static void make_map(PFN_tmEncode enc, CUtensorMap* m, void* ptr,
                     int box_inner, int box_outer)
{
    cuuint64_t dims[2]    = {4096, 4096};
    cuuint64_t strides[1] = {4096 * 2};
    cuuint32_t box[2]     = {(cuuint32_t)box_inner, (cuuint32_t)box_outer};
    cuuint32_t est[2]     = {1, 1};
    enc(m, CU_TENSOR_MAP_DATA_TYPE_FLOAT16, 2, ptr, dims, strides, box, est,
        CU_TENSOR_MAP_INTERLEAVE_NONE, CU_TENSOR_MAP_SWIZZLE_128B,
        CU_TENSOR_MAP_L2_PROMOTION_L2_128B, CU_TENSOR_MAP_FLOAT_OOB_FILL_NONE);
}

extern "C" void kernel_launch(void* const* d_in, const int* in_sizes, int n_in,
                              void* d_out, int out_size)
{
    const float* x    = (const float*)d_in[0];
    const float* w    = (const float*)d_in[1];
    const float* fast = (const float*)d_in[2];
    const float* slow = (const float*)d_in[3];

    float* out   = (float*)d_out;
    float* y_out = out;
    float* f_out = out + (size_t)TOK * DOUT;
    float* s_out = f_out + ELEMS;

    __half *wh, *xh, *yrh;
    cudaGetSymbolAddress((void**)&wh,  g_wh);
    cudaGetSymbolAddress((void**)&xh,  g_xh);
    cudaGetSymbolAddress((void**)&yrh, g_yrh);

    void* sym = nullptr;
    cudaDriverEntryPointQueryResult qr;
    cudaGetDriverEntryPoint("cuTensorMapEncodeTiled", &sym, cudaEnableDefault, &qr);
    PFN_tmEncode enc = (PFN_tmEncode)sym;

    // NT maps (GEMM1): box {64 k-elems, 128 rows}
    CUtensorMap mX, mW;
    make_map(enc, &mX, xh, 64, 128);
    make_map(enc, &mW, wh, 64, 128);
    // TT maps (GEMM2): box {64 cols, 64 k-rows}
    CUtensorMap mY, mXT;
    make_map(enc, &mY,  yrh, 64, 64);
    make_map(enc, &mXT, xh,  64, 64);

    cudaFuncSetAttribute(k_gemm_tma<0>, cudaFuncAttributeMaxDynamicSharedMemorySize, DYN_SMEM);
    cudaFuncSetAttribute(k_gemm_tma<1>, cudaFuncAttributeMaxDynamicSharedMemorySize, DYN_SMEM);

    // 1) fused prep: w_eff quantize->fp16 (single w read) AND X->fp16
    k_prep<<<4096 + 16384, 256>>>(w, fast, slow, x, wh, xh);
    // 2) Y = X @ w_eff^T; epilogue emits y fp32 + relu(Y) fp16
    k_gemm_tma<0><<<NTILES, 256, DYN_SMEM>>>(mX, mW, nullptr, y_out, yrh);
    // 3) new_fast (unscaled) = 0.95*fast + 0.05*(reluY^T @ X)/TOK, + partials
    k_gemm_tma<1><<<NTILES, 256, DYN_SMEM>>>(mY, mXT, fast, f_out, nullptr);
    // 4) norm -> factor
    k_norm_factor<<<1, 256>>>();
    // 5) scale fast, compute slow
    k_finalize<<<(unsigned)(ELEMS / 4 / 256), 256>>>(slow, f_out, s_out);
}